// round 2
// baseline (speedup 1.0000x reference)
#include <cuda_runtime.h>

#define NN 50000
#define EE 600000
#define LLM 640
#define HID 128
#define PO 112
#define SD 16

// ---------------- scratch (static device globals; no allocation) ------------
__device__ float g_x[(size_t)NN * HID];     // node features [N,128]
__device__ float g_xw[(size_t)NN * HID];    // x @ W per layer [N,128]
__device__ float g_dis[NN];                 // deg^{-1/2}
__device__ int   g_cnt[NN];                 // in-degree counts
__device__ int   g_rowptr[NN + 1];          // CSR row pointers (by dst)
__device__ int   g_pos[NN];                 // fill cursors
__device__ int   g_col[EE];                 // CSR column indices (src)

// ---------------- CSR build -------------------------------------------------
__global__ void zero_cnt_k() {
    int i = blockIdx.x * blockDim.x + threadIdx.x;
    if (i < NN) g_cnt[i] = 0;
}

__global__ void count_k(const int* __restrict__ dst) {
    int e = blockIdx.x * blockDim.x + threadIdx.x;
    if (e < EE) atomicAdd(&g_cnt[dst[e]], 1);
}

// Single-block scan: rowptr (exclusive->stored as rowptr[i+1]=incl), pos, dis.
__global__ void scan_k() {
    __shared__ int warp_tot[32];
    __shared__ int carry_s;
    int tid = threadIdx.x, lane = tid & 31, w = tid >> 5;
    if (tid == 0) { carry_s = 0; g_rowptr[0] = 0; }
    __syncthreads();
    for (int base = 0; base < NN; base += 1024) {
        int i = base + tid;
        int v = (i < NN) ? g_cnt[i] : 0;
        int x = v;
        #pragma unroll
        for (int o = 1; o < 32; o <<= 1) {
            int y = __shfl_up_sync(0xffffffffu, x, o);
            if (lane >= o) x += y;
        }
        if (lane == 31) warp_tot[w] = x;
        __syncthreads();
        if (w == 0) {
            int t = warp_tot[lane];
            #pragma unroll
            for (int o = 1; o < 32; o <<= 1) {
                int y = __shfl_up_sync(0xffffffffu, t, o);
                if (lane >= o) t += y;
            }
            warp_tot[lane] = t;
        }
        __syncthreads();
        int woff = (w > 0) ? warp_tot[w - 1] : 0;
        int incl = x + woff + carry_s;
        if (i < NN) {
            g_rowptr[i + 1] = incl;
            g_pos[i] = incl - v;
            g_dis[i] = rsqrtf(1.0f + (float)v);
        }
        __syncthreads();
        if (tid == 1023) carry_s = incl;   // v=0 for OOB tail -> incl == running total
        __syncthreads();
    }
}

__global__ void fill_k(const int* __restrict__ src, const int* __restrict__ dst) {
    int e = blockIdx.x * blockDim.x + threadIdx.x;
    if (e < EE) {
        int p = atomicAdd(&g_pos[dst[e]], 1);
        g_col[p] = src[e];
    }
}

// ---------------- projection GEMM: g_x[:, :112] = llm @ W + b ---------------
// BM=128, BN=112, BK=32, 256 threads, 8x7 register tile.
__global__ __launch_bounds__(256, 2) void proj_k(const float* __restrict__ A,
                                                 const float* __restrict__ W,
                                                 const float* __restrict__ bias) {
    __shared__ __align__(16) float As[128 * 33];
    __shared__ __align__(16) float Bs[32 * 112];
    int tid = threadIdx.x;
    int tx = tid & 15, ty = tid >> 4;
    int row0 = blockIdx.x * 128;
    float acc[8][7];
    #pragma unroll
    for (int r = 0; r < 8; r++)
        #pragma unroll
        for (int c = 0; c < 7; c++) acc[r][c] = 0.0f;

    for (int k0 = 0; k0 < LLM; k0 += 32) {
        // A tile: 128x32 floats = 1024 float4, 4 per thread
        #pragma unroll
        for (int i = 0; i < 4; i++) {
            int f = tid + i * 256;
            int r = f >> 3, c = (f & 7) * 4;
            int gr = row0 + r;
            float4 v = make_float4(0.f, 0.f, 0.f, 0.f);
            if (gr < NN) v = *(const float4*)(A + (size_t)gr * LLM + k0 + c);
            As[r * 33 + c + 0] = v.x;
            As[r * 33 + c + 1] = v.y;
            As[r * 33 + c + 2] = v.z;
            As[r * 33 + c + 3] = v.w;
        }
        // B tile: 32x112 floats = 896 float4
        for (int f = tid; f < 896; f += 256) {
            int r = f / 28, c = (f % 28) * 4;
            *(float4*)(Bs + r * 112 + c) = *(const float4*)(W + (size_t)(k0 + r) * 112 + c);
        }
        __syncthreads();
        #pragma unroll
        for (int k = 0; k < 32; k++) {
            float a[8], bb[7];
            #pragma unroll
            for (int r = 0; r < 8; r++) a[r] = As[(ty * 8 + r) * 33 + k];
            #pragma unroll
            for (int c = 0; c < 7; c++) bb[c] = Bs[k * 112 + tx * 7 + c];
            #pragma unroll
            for (int r = 0; r < 8; r++)
                #pragma unroll
                for (int c = 0; c < 7; c++) acc[r][c] = fmaf(a[r], bb[c], acc[r][c]);
        }
        __syncthreads();
    }
    #pragma unroll
    for (int r = 0; r < 8; r++) {
        int gr = row0 + ty * 8 + r;
        if (gr < NN) {
            #pragma unroll
            for (int c = 0; c < 7; c++) {
                int col = tx * 7 + c;
                g_x[(size_t)gr * HID + col] = acc[r][c] + bias[col];
            }
        }
    }
}

// ---------------- struct embedding concat: g_x[:, 112:128] -----------------
__global__ void struct_k(const int* __restrict__ ids, const float* __restrict__ emb) {
    int idx = blockIdx.x * blockDim.x + threadIdx.x;
    if (idx < NN * SD) {
        int i = idx >> 4, t = idx & 15;
        g_x[(size_t)i * HID + PO + t] = emb[ids[i] * SD + t];
    }
}

// ---------------- GCN GEMM: g_xw = g_x @ W (128x128) ------------------------
// BM=128, BN=128, BK=16, 256 threads, 8x8 register tile.
__global__ __launch_bounds__(256, 2) void gemm_k(const float* __restrict__ W) {
    __shared__ __align__(16) float As[128 * 17];
    __shared__ __align__(16) float Bs[16 * 128];
    int tid = threadIdx.x;
    int tx = tid & 15, ty = tid >> 4;
    int row0 = blockIdx.x * 128;
    float acc[8][8];
    #pragma unroll
    for (int r = 0; r < 8; r++)
        #pragma unroll
        for (int c = 0; c < 8; c++) acc[r][c] = 0.0f;

    for (int k0 = 0; k0 < HID; k0 += 16) {
        // A tile: 128x16 = 512 float4, 2 per thread
        #pragma unroll
        for (int i = 0; i < 2; i++) {
            int f = tid + i * 256;
            int r = f >> 2, c = (f & 3) * 4;
            int gr = row0 + r;
            float4 v = make_float4(0.f, 0.f, 0.f, 0.f);
            if (gr < NN) v = *(const float4*)(g_x + (size_t)gr * HID + k0 + c);
            As[r * 17 + c + 0] = v.x;
            As[r * 17 + c + 1] = v.y;
            As[r * 17 + c + 2] = v.z;
            As[r * 17 + c + 3] = v.w;
        }
        // B tile: 16x128 = 512 float4
        #pragma unroll
        for (int i = 0; i < 2; i++) {
            int f = tid + i * 256;
            int r = f >> 5, c = (f & 31) * 4;
            *(float4*)(Bs + r * 128 + c) = *(const float4*)(W + (size_t)(k0 + r) * 128 + c);
        }
        __syncthreads();
        #pragma unroll
        for (int k = 0; k < 16; k++) {
            float a[8], bb[8];
            #pragma unroll
            for (int r = 0; r < 8; r++) a[r] = As[(ty * 8 + r) * 17 + k];
            #pragma unroll
            for (int c = 0; c < 8; c++) bb[c] = Bs[k * 128 + tx * 8 + c];
            #pragma unroll
            for (int r = 0; r < 8; r++)
                #pragma unroll
                for (int c = 0; c < 8; c++) acc[r][c] = fmaf(a[r], bb[c], acc[r][c]);
        }
        __syncthreads();
    }
    #pragma unroll
    for (int r = 0; r < 8; r++) {
        int gr = row0 + ty * 8 + r;
        if (gr < NN) {
            #pragma unroll
            for (int c = 0; c < 4; c += 1) {}
            float4* out = (float4*)(g_xw + (size_t)gr * HID + tx * 8);
            out[0] = make_float4(acc[r][0], acc[r][1], acc[r][2], acc[r][3]);
            out[1] = make_float4(acc[r][4], acc[r][5], acc[r][6], acc[r][7]);
        }
    }
}

// ---------------- aggregation + self-loop + bias + relu + residual ----------
// one warp per node; lane handles 4 contiguous cols (float4)
__global__ void agg_k(const float* __restrict__ bias) {
    int warp = threadIdx.x >> 5, lane = threadIdx.x & 31;
    int row = blockIdx.x * 8 + warp;
    if (row >= NN) return;
    const float4* xw4 = (const float4*)g_xw;
    float4 acc = make_float4(0.f, 0.f, 0.f, 0.f);
    int e = g_rowptr[row], end = g_rowptr[row + 1];
    for (; e < end; e++) {
        int s = g_col[e];
        float w = g_dis[s];
        float4 v = xw4[(size_t)s * 32 + lane];
        acc.x += w * v.x; acc.y += w * v.y; acc.z += w * v.z; acc.w += w * v.w;
    }
    float d = g_dis[row];
    float dd = d * d;
    float4 sv = xw4[(size_t)row * 32 + lane];
    float4 bb = ((const float4*)bias)[lane];
    float4 r;
    r.x = fmaxf(d * acc.x + dd * sv.x + bb.x, 0.f);
    r.y = fmaxf(d * acc.y + dd * sv.y + bb.y, 0.f);
    r.z = fmaxf(d * acc.z + dd * sv.z + bb.z, 0.f);
    r.w = fmaxf(d * acc.w + dd * sv.w + bb.w, 0.f);
    float4* x4 = (float4*)g_x;
    float4 xo = x4[(size_t)row * 32 + lane];
    xo.x += r.x; xo.y += r.y; xo.z += r.z; xo.w += r.w;
    x4[(size_t)row * 32 + lane] = xo;
}

// ---------------- final LayerNorm -> d_out ----------------------------------
__global__ void ln_k(const float* __restrict__ g, const float* __restrict__ b,
                     float* __restrict__ out) {
    int warp = threadIdx.x >> 5, lane = threadIdx.x & 31;
    int row = blockIdx.x * 8 + warp;
    if (row >= NN) return;
    float4 v = ((const float4*)g_x)[(size_t)row * 32 + lane];
    float s = v.x + v.y + v.z + v.w;
    float s2 = v.x * v.x + v.y * v.y + v.z * v.z + v.w * v.w;
    #pragma unroll
    for (int o = 16; o; o >>= 1) {
        s  += __shfl_xor_sync(0xffffffffu, s, o);
        s2 += __shfl_xor_sync(0xffffffffu, s2, o);
    }
    float mean = s * (1.0f / 128.0f);
    float var = s2 * (1.0f / 128.0f) - mean * mean;
    float rstd = rsqrtf(var + 1e-5f);
    float4 gg = ((const float4*)g)[lane];
    float4 bb = ((const float4*)b)[lane];
    float4 o4;
    o4.x = (v.x - mean) * rstd * gg.x + bb.x;
    o4.y = (v.y - mean) * rstd * gg.y + bb.y;
    o4.z = (v.z - mean) * rstd * gg.z + bb.z;
    o4.w = (v.w - mean) * rstd * gg.w + bb.w;
    ((float4*)out)[(size_t)row * 32 + lane] = o4;
}

// ---------------- launcher --------------------------------------------------
extern "C" void kernel_launch(void* const* d_in, const int* in_sizes, int n_in,
                              void* d_out, int out_size) {
    const float* llm = (const float*)d_in[0];
    const int*   ids = (const int*)d_in[1];
    const int*   ei  = (const int*)d_in[2];
    const float* pW  = (const float*)d_in[3];
    const float* pb  = (const float*)d_in[4];
    const float* emb = (const float*)d_in[5];
    const float* gW  = (const float*)d_in[6];
    const float* gb  = (const float*)d_in[7];
    const float* lg  = (const float*)d_in[8];
    const float* lb  = (const float*)d_in[9];
    const int* src = ei;
    const int* dst = ei + EE;

    const int MB = (NN + 127) / 128;          // 391 GEMM row blocks
    const int WB = (NN + 7) / 8;              // 6250 warp-per-node blocks

    zero_cnt_k<<<(NN + 255) / 256, 256>>>();
    count_k<<<(EE + 255) / 256, 256>>>(dst);
    scan_k<<<1, 1024>>>();
    fill_k<<<(EE + 255) / 256, 256>>>(src, dst);

    proj_k<<<MB, 256>>>(llm, pW, pb);
    struct_k<<<(NN * SD + 255) / 256, 256>>>(ids, emb);

    for (int l = 0; l < 2; l++) {
        gemm_k<<<MB, 256>>>(gW + (size_t)l * HID * HID);
        agg_k<<<WB, 256>>>(gb + (size_t)l * HID);
    }
    ln_k<<<WB, 256>>>(lg, lb, (float*)d_out);
}